// round 3
// baseline (speedup 1.0000x reference)
#include <cuda_runtime.h>
#include <cstdint>

// ---------------------------------------------------------------------------
// MinGRU layer: B=4, T=4096, D=1024, Di=2048
//   hg = x @ W_hg                      (16384x1024 @ 1024x4096)
//   c  = sigmoid(-gate), v = sigmoid(gate)*G(hidden), G(x)= x>=0 ? x+0.5 : sigmoid(x)
//   h_t = c_t*h_{t-1} + v_t, h_{-1} = max(prev_hidden, 1e-8)
//   out = h @ W_out                    (16384x2048 @ 2048x1024)
//   next_hidden = h[:, T-1]
// ---------------------------------------------------------------------------

constexpr int BBATCH = 4;
constexpr int TSEQ   = 4096;
constexpr int DDIM   = 1024;
constexpr int DI     = 2048;
constexpr int MROWS  = BBATCH * TSEQ;      // 16384
constexpr int NCHUNK = 32;
constexpr int CHLEN  = TSEQ / NCHUNK;      // 128
constexpr int NCHAN  = BBATCH * DI;        // 8192

// ---- scratch (static __device__ globals; no allocation) --------------------
__device__ float g_xr [(size_t)MROWS * DDIM];       //  64 MB  tf32-rounded x
__device__ float g_whr[(size_t)DDIM * 2 * DI];      //  16 MB  tf32-rounded W_hg
__device__ float g_wor[(size_t)DI * DDIM];          //   8 MB  tf32-rounded W_out
__device__ float g_c  [(size_t)MROWS * DI];         // 128 MB
__device__ float g_v  [(size_t)MROWS * DI];         // 128 MB
__device__ float g_h  [(size_t)MROWS * DI];         // 128 MB (tf32-rounded)
__device__ float g_chC[NCHAN * NCHUNK];
__device__ float g_chV[NCHAN * NCHUNK];
__device__ float g_hst[NCHAN * NCHUNK];

// ---- helpers ---------------------------------------------------------------
__device__ __forceinline__ float to_tf32(float x) {
    uint32_t u;
    asm("cvt.rna.tf32.f32 %0, %1;" : "=r"(u) : "f"(x));
    return __uint_as_float(u);
}

__device__ __forceinline__ void cp16(float* dst_smem, const float* src_gmem) {
    uint32_t a = (uint32_t)__cvta_generic_to_shared(dst_smem);
    asm volatile("cp.async.ca.shared.global [%0], [%1], 16;\n" :: "r"(a), "l"(src_gmem));
}
#define CP_COMMIT() asm volatile("cp.async.commit_group;\n")
#define CP_WAIT1()  asm volatile("cp.async.wait_group 1;\n")
#define CP_WAIT0()  asm volatile("cp.async.wait_group 0;\n")

__device__ __forceinline__ void mma_tf32(float d[4], const uint32_t a[4], const uint32_t b[2]) {
    asm volatile(
        "mma.sync.aligned.m16n8k8.row.col.f32.tf32.tf32.f32 "
        "{%0,%1,%2,%3}, {%4,%5,%6,%7}, {%8,%9}, {%0,%1,%2,%3};\n"
        : "+f"(d[0]), "+f"(d[1]), "+f"(d[2]), "+f"(d[3])
        : "r"(a[0]), "r"(a[1]), "r"(a[2]), "r"(a[3]), "r"(b[0]), "r"(b[1]));
}

__device__ __forceinline__ float sigmoidf_fast(float x) {
    return 1.0f / (1.0f + __expf(-x));
}

// ---- kernel 0: round x / W_hg / W_out to tf32 (rna) ------------------------
// segment layout in float4 units:
//   [0, NX4)                 : x      -> g_xr
//   [NX4, NX4+NW4)           : W_hg   -> g_whr
//   [NX4+NW4, NX4+NW4+NO4)   : W_out  -> g_wor
constexpr int NX4 = MROWS * DDIM / 4;
constexpr int NW4 = DDIM * 2 * DI / 4;
constexpr int NO4 = DI * DDIM / 4;

__global__ void k_round_all(const float* __restrict__ x,
                            const float* __restrict__ whg,
                            const float* __restrict__ wout) {
    int i = blockIdx.x * blockDim.x + threadIdx.x;
    const float4* src;
    float4* dst;
    int off;
    if (i < NX4)                 { src = (const float4*)x;    dst = (float4*)g_xr;  off = i; }
    else if (i < NX4 + NW4)      { src = (const float4*)whg;  dst = (float4*)g_whr; off = i - NX4; }
    else if (i < NX4 + NW4 + NO4){ src = (const float4*)wout; dst = (float4*)g_wor; off = i - NX4 - NW4; }
    else return;
    float4 a = src[off];
    float4 r;
    r.x = to_tf32(a.x); r.y = to_tf32(a.y); r.z = to_tf32(a.z); r.w = to_tf32(a.w);
    dst[off] = r;
}

// ---- GEMM tiling constants --------------------------------------------------
constexpr int BM = 128;
constexpr int BK = 32;
constexpr int ASTR = 36;   // A smem row stride (conflict-free fragment loads)
constexpr int BSTR = 136;  // B smem row stride
constexpr int SMEM_GEMM_BYTES = (2 * BM * ASTR + 2 * BK * BSTR) * 4;  // 71680

// ---- kernel 1: GEMM1 hg = xr @ whr, fused epilogue -> c, v -----------------
// Block computes hidden[:, n0:n0+64] and gate[:, n0:n0+64] together.
// Smem B-tile cols 0..63 = hidden channel cols, 64..127 = gate channel cols.
__device__ __forceinline__ void g1_load(int tid, int m0, int n0, int kt,
                                        float* as, float* bs) {
    const int k0 = kt * BK;
    #pragma unroll
    for (int i = 0; i < 4; i++) {            // A: 128x32 = 1024 float4
        int idx = tid + i * 256;
        int row = idx >> 3, c4 = (idx & 7) * 4;
        cp16(&as[row * ASTR + c4], &g_xr[(size_t)(m0 + row) * DDIM + k0 + c4]);
    }
    #pragma unroll
    for (int i = 0; i < 4; i++) {            // B: 32x128 = 1024 float4
        int idx = tid + i * 256;
        int row = idx >> 5, c4 = (idx & 31) * 4;
        int gcol = (c4 < 64) ? (n0 + c4) : (DI + n0 + (c4 - 64));
        cp16(&bs[row * BSTR + c4], &g_whr[(size_t)(k0 + row) * (2 * DI) + gcol]);
    }
}

__global__ void __launch_bounds__(256, 1) k_gemm1() {
    const int m0 = blockIdx.y * BM;
    const int n0 = blockIdx.x * 64;
    const int tid = threadIdx.x;
    const int wid = tid >> 5, lane = tid & 31;
    const int wm = wid & 3, wn = wid >> 2;       // 4 x 2 warp grid
    const int grp = lane >> 2, tg = lane & 3;

    extern __shared__ float smem[];
    float* As = smem;                            // [2][BM][ASTR]
    float* Bs = smem + 2 * BM * ASTR;            // [2][BK][BSTR]

    float acc[2][8][4];
    #pragma unroll
    for (int a = 0; a < 2; a++)
        #pragma unroll
        for (int b = 0; b < 8; b++)
            #pragma unroll
            for (int r = 0; r < 4; r++) acc[a][b][r] = 0.f;

    g1_load(tid, m0, n0, 0, As, Bs);
    CP_COMMIT();

    #pragma unroll 1
    for (int kt = 0; kt < DDIM / BK; kt++) {
        const int buf = kt & 1;
        if (kt + 1 < DDIM / BK) {
            g1_load(tid, m0, n0, kt + 1, As + (buf ^ 1) * BM * ASTR, Bs + (buf ^ 1) * BK * BSTR);
            CP_COMMIT();
            CP_WAIT1();
        } else {
            CP_WAIT0();
        }
        __syncthreads();
        const float* as = As + buf * BM * ASTR;
        const float* bs = Bs + buf * BK * BSTR;
        #pragma unroll
        for (int k8 = 0; k8 < 4; k8++) {
            const int k = k8 * 8;
            uint32_t a[2][4], b[8][2];
            #pragma unroll
            for (int mm = 0; mm < 2; mm++) {
                int r0 = wm * 32 + mm * 16 + grp;
                a[mm][0] = __float_as_uint(as[r0 * ASTR + k + tg]);
                a[mm][1] = __float_as_uint(as[(r0 + 8) * ASTR + k + tg]);
                a[mm][2] = __float_as_uint(as[r0 * ASTR + k + tg + 4]);
                a[mm][3] = __float_as_uint(as[(r0 + 8) * ASTR + k + tg + 4]);
            }
            #pragma unroll
            for (int jn = 0; jn < 8; jn++) {
                int col = ((jn < 4) ? (wn * 32 + jn * 8) : (64 + wn * 32 + (jn - 4) * 8)) + grp;
                b[jn][0] = __float_as_uint(bs[(k + tg) * BSTR + col]);
                b[jn][1] = __float_as_uint(bs[(k + tg + 4) * BSTR + col]);
            }
            #pragma unroll
            for (int mm = 0; mm < 2; mm++)
                #pragma unroll
                for (int jn = 0; jn < 8; jn++)
                    mma_tf32(acc[mm][jn], a[mm], b[jn]);
        }
        __syncthreads();
    }

    // epilogue: hidden = acc[..][0..3], gate = acc[..][4..7] (same channel col)
    #pragma unroll
    for (int mm = 0; mm < 2; mm++)
        #pragma unroll
        for (int jn = 0; jn < 4; jn++)
            #pragma unroll
            for (int r = 0; r < 4; r++) {
                float hv = acc[mm][jn][r];
                float gv = acc[mm][jn + 4][r];
                int row = m0 + wm * 32 + mm * 16 + grp + ((r >> 1) << 3);
                int col = n0 + wn * 32 + jn * 8 + tg * 2 + (r & 1);
                float cg = 1.0f / (1.0f + __expf(gv));       // sigmoid(-g)
                float z  = sigmoidf_fast(gv);                 // sigmoid(g)
                float G  = (hv >= 0.0f) ? (hv + 0.5f) : sigmoidf_fast(hv);
                size_t o = (size_t)row * DI + col;
                g_c[o] = cg;
                g_v[o] = z * G;
            }
}

// ---- kernel 2: per-chunk affine reduce (C, V) ------------------------------
__global__ void k_chunk_reduce() {
    int ch = blockIdx.x * blockDim.x + threadIdx.x;    // 0..8191
    int chunk = blockIdx.y;
    int b = ch >> 11, j = ch & (DI - 1);
    size_t base = ((size_t)(b * TSEQ + chunk * CHLEN)) * DI + j;
    float C = 1.f, V = 0.f;
    #pragma unroll 4
    for (int t = 0; t < CHLEN; t++) {
        float ct = g_c[base + (size_t)t * DI];
        float vt = g_v[base + (size_t)t * DI];
        V = fmaf(V, ct, vt);
        C *= ct;
    }
    g_chC[ch * NCHUNK + chunk] = C;
    g_chV[ch * NCHUNK + chunk] = V;
}

// ---- kernel 3: scan over chunk aggregates -> chunk start states ------------
__global__ void k_chunk_scan(const float* __restrict__ prev_hidden) {
    int ch = blockIdx.x * blockDim.x + threadIdx.x;
    if (ch >= NCHAN) return;
    float h = fmaxf(prev_hidden[ch], 1e-8f);
    #pragma unroll
    for (int k = 0; k < NCHUNK; k++) {
        g_hst[ch * NCHUNK + k] = h;
        h = fmaf(g_chC[ch * NCHUNK + k], h, g_chV[ch * NCHUNK + k]);
    }
}

// ---- kernel 4: replay, write h (tf32-rounded) + next_hidden ----------------
__global__ void k_scan_apply(float* __restrict__ next_hidden) {
    int ch = blockIdx.x * blockDim.x + threadIdx.x;
    int chunk = blockIdx.y;
    int b = ch >> 11, j = ch & (DI - 1);
    size_t base = ((size_t)(b * TSEQ + chunk * CHLEN)) * DI + j;
    float h = g_hst[ch * NCHUNK + chunk];
    #pragma unroll 4
    for (int t = 0; t < CHLEN; t++) {
        size_t o = base + (size_t)t * DI;
        h = fmaf(g_c[o], h, g_v[o]);
        g_h[o] = to_tf32(h);
    }
    if (chunk == NCHUNK - 1) next_hidden[ch] = h;
}

// ---- kernel 5: GEMM2 out = h @ wor -----------------------------------------
__device__ __forceinline__ void g2_load(int tid, int m0, int n0, int kt,
                                        float* as, float* bs) {
    const int k0 = kt * BK;
    #pragma unroll
    for (int i = 0; i < 4; i++) {
        int idx = tid + i * 256;
        int row = idx >> 3, c4 = (idx & 7) * 4;
        cp16(&as[row * ASTR + c4], &g_h[(size_t)(m0 + row) * DI + k0 + c4]);
    }
    #pragma unroll
    for (int i = 0; i < 4; i++) {
        int idx = tid + i * 256;
        int row = idx >> 5, c4 = (idx & 31) * 4;
        cp16(&bs[row * BSTR + c4], &g_wor[(size_t)(k0 + row) * DDIM + n0 + c4]);
    }
}

__global__ void __launch_bounds__(256, 1) k_gemm2(float* __restrict__ out) {
    const int m0 = blockIdx.y * BM;
    const int n0 = blockIdx.x * 128;
    const int tid = threadIdx.x;
    const int wid = tid >> 5, lane = tid & 31;
    const int wm = wid & 3, wn = wid >> 2;
    const int grp = lane >> 2, tg = lane & 3;

    extern __shared__ float smem[];
    float* As = smem;
    float* Bs = smem + 2 * BM * ASTR;

    float acc[2][8][4];
    #pragma unroll
    for (int a = 0; a < 2; a++)
        #pragma unroll
        for (int b = 0; b < 8; b++)
            #pragma unroll
            for (int r = 0; r < 4; r++) acc[a][b][r] = 0.f;

    g2_load(tid, m0, n0, 0, As, Bs);
    CP_COMMIT();

    #pragma unroll 1
    for (int kt = 0; kt < DI / BK; kt++) {
        const int buf = kt & 1;
        if (kt + 1 < DI / BK) {
            g2_load(tid, m0, n0, kt + 1, As + (buf ^ 1) * BM * ASTR, Bs + (buf ^ 1) * BK * BSTR);
            CP_COMMIT();
            CP_WAIT1();
        } else {
            CP_WAIT0();
        }
        __syncthreads();
        const float* as = As + buf * BM * ASTR;
        const float* bs = Bs + buf * BK * BSTR;
        #pragma unroll
        for (int k8 = 0; k8 < 4; k8++) {
            const int k = k8 * 8;
            uint32_t a[2][4], b[8][2];
            #pragma unroll
            for (int mm = 0; mm < 2; mm++) {
                int r0 = wm * 32 + mm * 16 + grp;
                a[mm][0] = __float_as_uint(as[r0 * ASTR + k + tg]);
                a[mm][1] = __float_as_uint(as[(r0 + 8) * ASTR + k + tg]);
                a[mm][2] = __float_as_uint(as[r0 * ASTR + k + tg + 4]);
                a[mm][3] = __float_as_uint(as[(r0 + 8) * ASTR + k + tg + 4]);
            }
            #pragma unroll
            for (int jn = 0; jn < 8; jn++) {
                int col = wn * 64 + jn * 8 + grp;
                b[jn][0] = __float_as_uint(bs[(k + tg) * BSTR + col]);
                b[jn][1] = __float_as_uint(bs[(k + tg + 4) * BSTR + col]);
            }
            #pragma unroll
            for (int mm = 0; mm < 2; mm++)
                #pragma unroll
                for (int jn = 0; jn < 8; jn++)
                    mma_tf32(acc[mm][jn], a[mm], b[jn]);
        }
        __syncthreads();
    }

    #pragma unroll
    for (int mm = 0; mm < 2; mm++)
        #pragma unroll
        for (int jn = 0; jn < 8; jn++)
            #pragma unroll
            for (int r = 0; r < 4; r++) {
                int row = m0 + wm * 32 + mm * 16 + grp + ((r >> 1) << 3);
                int col = n0 + wn * 64 + jn * 8 + tg * 2 + (r & 1);
                out[(size_t)row * DDIM + col] = acc[mm][jn][r];
            }
}

// ---------------------------------------------------------------------------
extern "C" void kernel_launch(void* const* d_in, const int* in_sizes, int n_in,
                              void* d_out, int out_size) {
    const float* x    = (const float*)d_in[0];   // (4, 4096, 1024)
    const float* prev = (const float*)d_in[1];   // (4, 2048)
    const float* whg  = (const float*)d_in[2];   // (1024, 4096)
    const float* wout = (const float*)d_in[3];   // (2048, 1024)
    float* out = (float*)d_out;                  // out (16777216) + next_hidden (8192)
    float* next_hidden = out + (size_t)MROWS * DDIM;

    cudaFuncSetAttribute(k_gemm1, cudaFuncAttributeMaxDynamicSharedMemorySize, SMEM_GEMM_BYTES);
    cudaFuncSetAttribute(k_gemm2, cudaFuncAttributeMaxDynamicSharedMemorySize, SMEM_GEMM_BYTES);

    // 0) tf32 rounding (rna — avoids truncation bias)
    {
        int total4 = NX4 + NW4 + NO4;
        k_round_all<<<(total4 + 255) / 256, 256>>>(x, whg, wout);
    }
    // 1) GEMM1 + c/v epilogue
    {
        dim3 grid(DI / 64, MROWS / BM);          // 32 x 128
        k_gemm1<<<grid, 256, SMEM_GEMM_BYTES>>>();
    }
    // 2) chunk reduce
    {
        dim3 grid(NCHAN / 256, NCHUNK);          // 32 x 32
        k_chunk_reduce<<<grid, 256>>>();
    }
    // 3) chunk-aggregate scan
    k_chunk_scan<<<NCHAN / 256, 256>>>(prev);
    // 4) replay -> h, next_hidden
    {
        dim3 grid(NCHAN / 256, NCHUNK);
        k_scan_apply<<<grid, 256>>>(next_hidden);
    }
    // 5) GEMM2 -> out
    {
        dim3 grid(DDIM / 128, MROWS / BM);       // 8 x 128
        k_gemm2<<<grid, 256, SMEM_GEMM_BYTES>>>(out);
    }
}

// round 5
// speedup vs baseline: 1.1521x; 1.1521x over previous
#include <cuda_runtime.h>
#include <cstdint>

// ---------------------------------------------------------------------------
// MinGRU layer: B=4, T=4096, D=1024, Di=2048   (legacy mma.sync tf32 path —
// harness compiles via compute_103 virtual arch, so tcgen05 is unavailable)
//   hg = x @ W_hg ; c = sigmoid(-gate); v = sigmoid(gate)*G(hidden)
//   h_t = c_t*h_{t-1} + v_t, h_{-1} = max(prev_hidden, 1e-8)
//   out = h @ W_out ; next_hidden = h[:, T-1]
// ---------------------------------------------------------------------------

constexpr int BBATCH = 4;
constexpr int TSEQ   = 4096;
constexpr int DDIM   = 1024;
constexpr int DI     = 2048;
constexpr int MROWS  = BBATCH * TSEQ;      // 16384
constexpr int NCHUNK = 32;
constexpr int CHLEN  = TSEQ / NCHUNK;      // 128 == GEMM1 M-tile
constexpr int NCHAN  = BBATCH * DI;        // 8192

// ---- scratch (static __device__ globals; no allocation) --------------------
__device__ float g_xr [(size_t)MROWS * DDIM];       //  64 MB  tf32-rounded x
__device__ float g_whr[(size_t)DDIM * 2 * DI];      //  16 MB  tf32-rounded W_hg
__device__ float g_wor[(size_t)DI * DDIM];          //   8 MB  tf32-rounded W_out
__device__ float g_c  [(size_t)MROWS * DI];         // 128 MB
__device__ float g_v  [(size_t)MROWS * DI];         // 128 MB
__device__ float g_h  [(size_t)MROWS * DI];         // 128 MB (tf32-rounded)
__device__ float g_chC[NCHAN * NCHUNK];
__device__ float g_chV[NCHAN * NCHUNK];
__device__ float g_hst[NCHAN * NCHUNK];

// ---- helpers ---------------------------------------------------------------
__device__ __forceinline__ float to_tf32(float x) {
    uint32_t u;
    asm("cvt.rna.tf32.f32 %0, %1;" : "=r"(u) : "f"(x));
    return __uint_as_float(u);
}

__device__ __forceinline__ void cp16(float* dst_smem, const float* src_gmem) {
    uint32_t a = (uint32_t)__cvta_generic_to_shared(dst_smem);
    asm volatile("cp.async.ca.shared.global [%0], [%1], 16;\n" :: "r"(a), "l"(src_gmem));
}
#define CP_COMMIT() asm volatile("cp.async.commit_group;\n")
#define CP_WAIT1()  asm volatile("cp.async.wait_group 1;\n")
#define CP_WAIT0()  asm volatile("cp.async.wait_group 0;\n")

__device__ __forceinline__ void mma_tf32(float d[4], const uint32_t a[4], const uint32_t b[2]) {
    asm volatile(
        "mma.sync.aligned.m16n8k8.row.col.f32.tf32.tf32.f32 "
        "{%0,%1,%2,%3}, {%4,%5,%6,%7}, {%8,%9}, {%0,%1,%2,%3};\n"
        : "+f"(d[0]), "+f"(d[1]), "+f"(d[2]), "+f"(d[3])
        : "r"(a[0]), "r"(a[1]), "r"(a[2]), "r"(a[3]), "r"(b[0]), "r"(b[1]));
}

__device__ __forceinline__ float sigmoidf_fast(float x) {
    return 1.0f / (1.0f + __expf(-x));
}

// ---- kernel 0: round x / W_hg / W_out to tf32 (rna) ------------------------
constexpr int NX4 = MROWS * DDIM / 4;
constexpr int NW4 = DDIM * 2 * DI / 4;
constexpr int NO4 = DI * DDIM / 4;

__global__ void k_round_all(const float* __restrict__ x,
                            const float* __restrict__ whg,
                            const float* __restrict__ wout) {
    int i = blockIdx.x * blockDim.x + threadIdx.x;
    const float4* src;
    float4* dst;
    int off;
    if (i < NX4)                 { src = (const float4*)x;    dst = (float4*)g_xr;  off = i; }
    else if (i < NX4 + NW4)      { src = (const float4*)whg;  dst = (float4*)g_whr; off = i - NX4; }
    else if (i < NX4 + NW4 + NO4){ src = (const float4*)wout; dst = (float4*)g_wor; off = i - NX4 - NW4; }
    else return;
    float4 a = src[off];
    float4 r;
    r.x = to_tf32(a.x); r.y = to_tf32(a.y); r.z = to_tf32(a.z); r.w = to_tf32(a.w);
    dst[off] = r;
}

// ---- GEMM tiling constants --------------------------------------------------
constexpr int BM = 128;
constexpr int BK = 32;
constexpr int ASTR = 36;   // A smem row stride
constexpr int BSTR = 136;  // B smem row stride
constexpr int SMEM_GEMM_BYTES = (2 * BM * ASTR + 2 * BK * BSTR) * 4;  // 71680
// epilogue staging (reuses the same dynamic smem):
constexpr int ESTR1 = 68;   // 128x64 c + v tiles, stride 68 floats
constexpr int ESTR2 = 132;  // 128x128 out tile,   stride 132 floats
static_assert(2 * 128 * ESTR1 * 4 <= SMEM_GEMM_BYTES, "epi1 fits");
static_assert(128 * ESTR2 * 4 <= SMEM_GEMM_BYTES, "epi2 fits");

// ---- kernel 1: GEMM1 hg = xr @ whr, fused epilogue -> c, v + chunk reduce --
__device__ __forceinline__ void g1_load(int tid, int m0, int n0, int kt,
                                        float* as, float* bs) {
    const int k0 = kt * BK;
    #pragma unroll
    for (int i = 0; i < 4; i++) {            // A: 128x32
        int idx = tid + i * 256;
        int row = idx >> 3, c4 = (idx & 7) * 4;
        cp16(&as[row * ASTR + c4], &g_xr[(size_t)(m0 + row) * DDIM + k0 + c4]);
    }
    #pragma unroll
    for (int i = 0; i < 4; i++) {            // B: 32x128 (hidden cols | gate cols)
        int idx = tid + i * 256;
        int row = idx >> 5, c4 = (idx & 31) * 4;
        int gcol = (c4 < 64) ? (n0 + c4) : (DI + n0 + (c4 - 64));
        cp16(&bs[row * BSTR + c4], &g_whr[(size_t)(k0 + row) * (2 * DI) + gcol]);
    }
}

__global__ void __launch_bounds__(256, 2) k_gemm1() {
    const int m0 = blockIdx.y * BM;
    const int n0 = blockIdx.x * 64;
    const int tid = threadIdx.x;
    const int wid = tid >> 5, lane = tid & 31;
    const int wm = wid & 3, wn = wid >> 2;       // 4 x 2 warp grid
    const int grp = lane >> 2, tg = lane & 3;

    extern __shared__ float smem[];
    float* As = smem;                            // [2][BM][ASTR]
    float* Bs = smem + 2 * BM * ASTR;            // [2][BK][BSTR]

    float acc[2][8][4];
    #pragma unroll
    for (int a = 0; a < 2; a++)
        #pragma unroll
        for (int b = 0; b < 8; b++)
            #pragma unroll
            for (int r = 0; r < 4; r++) acc[a][b][r] = 0.f;

    g1_load(tid, m0, n0, 0, As, Bs);
    CP_COMMIT();

    #pragma unroll 1
    for (int kt = 0; kt < DDIM / BK; kt++) {
        const int buf = kt & 1;
        if (kt + 1 < DDIM / BK) {
            g1_load(tid, m0, n0, kt + 1, As + (buf ^ 1) * BM * ASTR, Bs + (buf ^ 1) * BK * BSTR);
            CP_COMMIT();
            CP_WAIT1();
        } else {
            CP_WAIT0();
        }
        __syncthreads();
        const float* as = As + buf * BM * ASTR;
        const float* bs = Bs + buf * BK * BSTR;
        #pragma unroll
        for (int k8 = 0; k8 < 4; k8++) {
            const int k = k8 * 8;
            uint32_t a[2][4], b[8][2];
            #pragma unroll
            for (int mm = 0; mm < 2; mm++) {
                int r0 = wm * 32 + mm * 16 + grp;
                a[mm][0] = __float_as_uint(as[r0 * ASTR + k + tg]);
                a[mm][1] = __float_as_uint(as[(r0 + 8) * ASTR + k + tg]);
                a[mm][2] = __float_as_uint(as[r0 * ASTR + k + tg + 4]);
                a[mm][3] = __float_as_uint(as[(r0 + 8) * ASTR + k + tg + 4]);
            }
            #pragma unroll
            for (int jn = 0; jn < 8; jn++) {
                int col = ((jn < 4) ? (wn * 32 + jn * 8) : (64 + wn * 32 + (jn - 4) * 8)) + grp;
                b[jn][0] = __float_as_uint(bs[(k + tg) * BSTR + col]);
                b[jn][1] = __float_as_uint(bs[(k + tg + 4) * BSTR + col]);
            }
            #pragma unroll
            for (int mm = 0; mm < 2; mm++)
                #pragma unroll
                for (int jn = 0; jn < 8; jn++)
                    mma_tf32(acc[mm][jn], a[mm], b[jn]);
        }
        __syncthreads();
    }

    // ---- epilogue: c/v -> smem (coalesced store + fused chunk reduce) ------
    float* sc = smem;                     // [128][ESTR1]
    float* sv = smem + 128 * ESTR1;       // [128][ESTR1]
    #pragma unroll
    for (int mm = 0; mm < 2; mm++)
        #pragma unroll
        for (int jn = 0; jn < 4; jn++)
            #pragma unroll
            for (int r = 0; r < 4; r++) {
                float hv = acc[mm][jn][r];
                float gv = acc[mm][jn + 4][r];
                int rl = wm * 32 + mm * 16 + grp + ((r >> 1) << 3);
                int cl = wn * 32 + jn * 8 + tg * 2 + (r & 1);
                float e  = __expf(gv);
                float ci = 1.0f / (1.0f + e);        // sigmoid(-g)
                float z  = 1.0f - ci;                // sigmoid(g)
                float G  = (hv >= 0.0f) ? (hv + 0.5f) : sigmoidf_fast(hv);
                sc[rl * ESTR1 + cl] = ci;
                sv[rl * ESTR1 + cl] = z * G;
            }
    __syncthreads();

    // coalesced float4 writes of the 128x64 c/v tiles
    #pragma unroll
    for (int q = 0; q < 8; q++) {
        int idx = tid + q * 256;               // 0..2047
        int row = idx >> 4, c4 = (idx & 15) * 4;
        float4 vc = *(const float4*)&sc[row * ESTR1 + c4];
        float4 vv = *(const float4*)&sv[row * ESTR1 + c4];
        *(float4*)&g_c[(size_t)(m0 + row) * DI + n0 + c4] = vc;
        *(float4*)&g_v[(size_t)(m0 + row) * DI + n0 + c4] = vv;
    }

    // fused chunk reduce: this tile IS one scan chunk (128 consecutive t)
    {
        const int batch = m0 >> 12;            // m0 / 4096
        const int chunk = (m0 & 4095) >> 7;    // (m0 % 4096) / 128
        #pragma unroll 1
        for (int cc = 0; cc < 8; cc++) {
            const int colL = wid * 8 + cc;     // 8 warps x 8 cols = 64
            float C = 1.f, V = 0.f;
            #pragma unroll
            for (int rb = 0; rb < 4; rb++) {
                float c_ = sc[(rb * 32 + lane) * ESTR1 + colL];
                float v_ = sv[(rb * 32 + lane) * ESTR1 + colL];
                // order-preserving tree reduce over 32 lanes (lane = time order)
                #pragma unroll
                for (int off = 1; off < 32; off <<= 1) {
                    float ch = __shfl_down_sync(0xffffffffu, c_, off);
                    float vh = __shfl_down_sync(0xffffffffu, v_, off);
                    v_ = fmaf(ch, v_, vh);     // later o earlier
                    c_ *= ch;
                }
                c_ = __shfl_sync(0xffffffffu, c_, 0);
                v_ = __shfl_sync(0xffffffffu, v_, 0);
                V = fmaf(c_, V, v_);           // compose sub-block (later) onto running
                C *= c_;
            }
            if (lane == 0) {
                int ch = batch * DI + n0 + colL;
                g_chC[ch * NCHUNK + chunk] = C;
                g_chV[ch * NCHUNK + chunk] = V;
            }
        }
    }
}

// ---- kernel 3: scan over chunk aggregates -> chunk start states ------------
__global__ void k_chunk_scan(const float* __restrict__ prev_hidden) {
    int ch = blockIdx.x * blockDim.x + threadIdx.x;
    if (ch >= NCHAN) return;
    float h = fmaxf(prev_hidden[ch], 1e-8f);
    #pragma unroll
    for (int k = 0; k < NCHUNK; k++) {
        g_hst[ch * NCHUNK + k] = h;
        h = fmaf(g_chC[ch * NCHUNK + k], h, g_chV[ch * NCHUNK + k]);
    }
}

// ---- kernel 4: replay, write h (tf32-rounded) + next_hidden ----------------
__global__ void k_scan_apply(float* __restrict__ next_hidden) {
    int ch = blockIdx.x * blockDim.x + threadIdx.x;
    int chunk = blockIdx.y;
    int b = ch >> 11, j = ch & (DI - 1);
    size_t base = ((size_t)(b * TSEQ + chunk * CHLEN)) * DI + j;
    float h = g_hst[ch * NCHUNK + chunk];
    #pragma unroll 4
    for (int t = 0; t < CHLEN; t++) {
        size_t o = base + (size_t)t * DI;
        h = fmaf(g_c[o], h, g_v[o]);
        g_h[o] = to_tf32(h);
    }
    if (chunk == NCHUNK - 1) next_hidden[ch] = h;
}

// ---- kernel 5: GEMM2 out = h @ wor -----------------------------------------
__device__ __forceinline__ void g2_load(int tid, int m0, int n0, int kt,
                                        float* as, float* bs) {
    const int k0 = kt * BK;
    #pragma unroll
    for (int i = 0; i < 4; i++) {
        int idx = tid + i * 256;
        int row = idx >> 3, c4 = (idx & 7) * 4;
        cp16(&as[row * ASTR + c4], &g_h[(size_t)(m0 + row) * DI + k0 + c4]);
    }
    #pragma unroll
    for (int i = 0; i < 4; i++) {
        int idx = tid + i * 256;
        int row = idx >> 5, c4 = (idx & 31) * 4;
        cp16(&bs[row * BSTR + c4], &g_wor[(size_t)(k0 + row) * DDIM + n0 + c4]);
    }
}

__global__ void __launch_bounds__(256, 2) k_gemm2(float* __restrict__ out) {
    const int m0 = blockIdx.y * BM;
    const int n0 = blockIdx.x * 128;
    const int tid = threadIdx.x;
    const int wid = tid >> 5, lane = tid & 31;
    const int wm = wid & 3, wn = wid >> 2;
    const int grp = lane >> 2, tg = lane & 3;

    extern __shared__ float smem[];
    float* As = smem;
    float* Bs = smem + 2 * BM * ASTR;

    float acc[2][8][4];
    #pragma unroll
    for (int a = 0; a < 2; a++)
        #pragma unroll
        for (int b = 0; b < 8; b++)
            #pragma unroll
            for (int r = 0; r < 4; r++) acc[a][b][r] = 0.f;

    g2_load(tid, m0, n0, 0, As, Bs);
    CP_COMMIT();

    #pragma unroll 1
    for (int kt = 0; kt < DI / BK; kt++) {
        const int buf = kt & 1;
        if (kt + 1 < DI / BK) {
            g2_load(tid, m0, n0, kt + 1, As + (buf ^ 1) * BM * ASTR, Bs + (buf ^ 1) * BK * BSTR);
            CP_COMMIT();
            CP_WAIT1();
        } else {
            CP_WAIT0();
        }
        __syncthreads();
        const float* as = As + buf * BM * ASTR;
        const float* bs = Bs + buf * BK * BSTR;
        #pragma unroll
        for (int k8 = 0; k8 < 4; k8++) {
            const int k = k8 * 8;
            uint32_t a[2][4], b[8][2];
            #pragma unroll
            for (int mm = 0; mm < 2; mm++) {
                int r0 = wm * 32 + mm * 16 + grp;
                a[mm][0] = __float_as_uint(as[r0 * ASTR + k + tg]);
                a[mm][1] = __float_as_uint(as[(r0 + 8) * ASTR + k + tg]);
                a[mm][2] = __float_as_uint(as[r0 * ASTR + k + tg + 4]);
                a[mm][3] = __float_as_uint(as[(r0 + 8) * ASTR + k + tg + 4]);
            }
            #pragma unroll
            for (int jn = 0; jn < 8; jn++) {
                int col = wn * 64 + jn * 8 + grp;
                b[jn][0] = __float_as_uint(bs[(k + tg) * BSTR + col]);
                b[jn][1] = __float_as_uint(bs[(k + tg + 4) * BSTR + col]);
            }
            #pragma unroll
            for (int mm = 0; mm < 2; mm++)
                #pragma unroll
                for (int jn = 0; jn < 8; jn++)
                    mma_tf32(acc[mm][jn], a[mm], b[jn]);
        }
        __syncthreads();
    }

    // ---- epilogue: stage 128x128 tile in smem, coalesced float4 stores -----
    float* so = smem;                          // [128][ESTR2]
    #pragma unroll
    for (int mm = 0; mm < 2; mm++)
        #pragma unroll
        for (int jn = 0; jn < 8; jn++)
            #pragma unroll
            for (int r = 0; r < 4; r++) {
                int rl = wm * 32 + mm * 16 + grp + ((r >> 1) << 3);
                int cl = wn * 64 + jn * 8 + tg * 2 + (r & 1);
                so[rl * ESTR2 + cl] = acc[mm][jn][r];
            }
    __syncthreads();
    #pragma unroll
    for (int q = 0; q < 16; q++) {
        int idx = tid + q * 256;               // 0..4095
        int row = idx >> 5, c4 = (idx & 31) * 4;
        float4 vv = *(const float4*)&so[row * ESTR2 + c4];
        *(float4*)&out[(size_t)(m0 + row) * DDIM + n0 + c4] = vv;
    }
}

// ---------------------------------------------------------------------------
extern "C" void kernel_launch(void* const* d_in, const int* in_sizes, int n_in,
                              void* d_out, int out_size) {
    const float* x    = (const float*)d_in[0];   // (4, 4096, 1024)
    const float* prev = (const float*)d_in[1];   // (4, 2048)
    const float* whg  = (const float*)d_in[2];   // (1024, 4096)
    const float* wout = (const float*)d_in[3];   // (2048, 1024)
    float* out = (float*)d_out;                  // out (16777216) + next_hidden (8192)
    float* next_hidden = out + (size_t)MROWS * DDIM;

    cudaFuncSetAttribute(k_gemm1, cudaFuncAttributeMaxDynamicSharedMemorySize, SMEM_GEMM_BYTES);
    cudaFuncSetAttribute(k_gemm2, cudaFuncAttributeMaxDynamicSharedMemorySize, SMEM_GEMM_BYTES);

    // 0) tf32 rounding (rna)
    {
        int total4 = NX4 + NW4 + NO4;
        k_round_all<<<(total4 + 255) / 256, 256>>>(x, whg, wout);
    }
    // 1) GEMM1 + c/v epilogue + fused per-chunk affine reduce
    {
        dim3 grid(DI / 64, MROWS / BM);          // 32 x 128
        k_gemm1<<<grid, 256, SMEM_GEMM_BYTES>>>();
    }
    // 2) chunk-aggregate scan
    k_chunk_scan<<<NCHAN / 256, 256>>>(prev);
    // 3) replay -> h, next_hidden
    {
        dim3 grid(NCHAN / 256, NCHUNK);
        k_scan_apply<<<grid, 256>>>(next_hidden);
    }
    // 4) GEMM2 -> out
    {
        dim3 grid(DDIM / 128, MROWS / BM);       // 8 x 128
        k_gemm2<<<grid, 256, SMEM_GEMM_BYTES>>>(out);
    }
}

// round 7
// speedup vs baseline: 1.9358x; 1.6802x over previous
#include <cuda_runtime.h>
#include <cuda_fp16.h>
#include <cstdint>

// ---------------------------------------------------------------------------
// MinGRU layer: B=4, T=4096, D=1024, Di=2048   (legacy mma.sync path — the
// harness compiles via compute_103 virtual arch, so tcgen05 is unavailable.
// fp16 m16n8k16 has the SAME 10-bit mantissa as tf32 but 2x the HMMA rate.)
//   hg = x @ W_hg ; c = sigmoid(-gate); v = sigmoid(gate)*G(hidden)
//   h_t = c_t*h_{t-1} + v_t, h_{-1} = max(prev_hidden, 1e-8)
//   out = h @ W_out ; next_hidden = h[:, T-1]
// ---------------------------------------------------------------------------

constexpr int BBATCH = 4;
constexpr int TSEQ   = 4096;
constexpr int DDIM   = 1024;
constexpr int DI     = 2048;
constexpr int MROWS  = BBATCH * TSEQ;      // 16384
constexpr int NCHUNK = 32;
constexpr int CHLEN  = TSEQ / NCHUNK;      // 128 == GEMM1 M-tile
constexpr int NCHAN  = BBATCH * DI;        // 8192

// ---- scratch (static __device__ globals; no allocation) --------------------
__device__ __half g_xh [(size_t)MROWS * DDIM];      //  32 MB  fp16 x
__device__ __half g_whT[(size_t)(2 * DI) * DDIM];   //   8 MB  W_hg^T fp16 [4096][1024]
__device__ __half g_woT[(size_t)DDIM * DI];         //   4 MB  W_out^T fp16 [1024][2048]
__device__ float  g_c  [(size_t)MROWS * DI];        // 128 MB
__device__ float  g_v  [(size_t)MROWS * DI];        // 128 MB
__device__ __half g_hh [(size_t)MROWS * DI];        //  64 MB  fp16 h
__device__ float  g_chC[NCHAN * NCHUNK];
__device__ float  g_chV[NCHAN * NCHUNK];
__device__ float  g_hst[NCHAN * NCHUNK];

// ---- helpers ---------------------------------------------------------------
__device__ __forceinline__ void cp16(const __half* dst_smem, const __half* src_gmem) {
    uint32_t a = (uint32_t)__cvta_generic_to_shared(dst_smem);
    asm volatile("cp.async.ca.shared.global [%0], [%1], 16;\n" :: "r"(a), "l"(src_gmem));
}
#define CP_COMMIT() asm volatile("cp.async.commit_group;\n")
#define CP_WAIT1()  asm volatile("cp.async.wait_group 1;\n")
#define CP_WAIT0()  asm volatile("cp.async.wait_group 0;\n")

__device__ __forceinline__ void mma_f16(float d[4], const uint32_t a[4], const uint32_t b[2]) {
    asm volatile(
        "mma.sync.aligned.m16n8k16.row.col.f32.f16.f16.f32 "
        "{%0,%1,%2,%3}, {%4,%5,%6,%7}, {%8,%9}, {%0,%1,%2,%3};\n"
        : "+f"(d[0]), "+f"(d[1]), "+f"(d[2]), "+f"(d[3])
        : "r"(a[0]), "r"(a[1]), "r"(a[2]), "r"(a[3]), "r"(b[0]), "r"(b[1]));
}

__device__ __forceinline__ uint32_t ldu32(const __half* p) {
    return *(const uint32_t*)p;
}

__device__ __forceinline__ float sigmoidf_fast(float x) {
    return 1.0f / (1.0f + __expf(-x));
}

// ---- kernel 0a: x fp32 -> fp16 (rne) ---------------------------------------
__global__ void k_conv_x(const float4* __restrict__ x) {
    int i = blockIdx.x * blockDim.x + threadIdx.x;   // handles 8 floats
    float4 a = x[2 * i], b = x[2 * i + 1];
    __half2 h0 = __floats2half2_rn(a.x, a.y);
    __half2 h1 = __floats2half2_rn(a.z, a.w);
    __half2 h2 = __floats2half2_rn(b.x, b.y);
    __half2 h3 = __floats2half2_rn(b.z, b.w);
    uint4 o;
    o.x = *(uint32_t*)&h0; o.y = *(uint32_t*)&h1;
    o.z = *(uint32_t*)&h2; o.w = *(uint32_t*)&h3;
    ((uint4*)g_xh)[i] = o;
}

// ---- kernel 0b/0c: weight transpose + fp16 convert -------------------------
__global__ void k_trans_whg(const float* __restrict__ w) {   // [1024][4096] -> [4096][1024]
    __shared__ float t[32][33];
    int bx = blockIdx.x * 32, by = blockIdx.y * 32;
    int x = threadIdx.x, y = threadIdx.y;
    #pragma unroll
    for (int i = 0; i < 32; i += 8)
        t[y + i][x] = w[(size_t)(by + y + i) * (2 * DI) + bx + x];
    __syncthreads();
    #pragma unroll
    for (int i = 0; i < 32; i += 8)
        g_whT[(size_t)(bx + y + i) * DDIM + by + x] = __float2half_rn(t[x][y + i]);
}

__global__ void k_trans_wout(const float* __restrict__ w) {  // [2048][1024] -> [1024][2048]
    __shared__ float t[32][33];
    int bx = blockIdx.x * 32, by = blockIdx.y * 32;
    int x = threadIdx.x, y = threadIdx.y;
    #pragma unroll
    for (int i = 0; i < 32; i += 8)
        t[y + i][x] = w[(size_t)(by + y + i) * DDIM + bx + x];
    __syncthreads();
    #pragma unroll
    for (int i = 0; i < 32; i += 8)
        g_woT[(size_t)(bx + y + i) * DI + by + x] = __float2half_rn(t[x][y + i]);
}

// ---- GEMM tiling constants --------------------------------------------------
constexpr int BM    = 128;
constexpr int BK    = 64;                       // halves per k-tile
constexpr int STRH  = 72;                       // smem row stride in halves (144B, 16B-aligned, conflict-free)
constexpr int ATILE = BM * STRH;                // halves per A buffer
constexpr int BTILE = 128 * STRH;               // halves per B buffer (128 n-rows)
constexpr int SMEM_GEMM_BYTES = 2 * (ATILE + BTILE) * 2;  // 73728
// epilogue staging (reuses the same dynamic smem):
constexpr int ESTR1 = 68;   // 128x64 c + v tiles (floats)
constexpr int ESTR2 = 132;  // 128x128 out tile  (floats)
static_assert(2 * 128 * ESTR1 * 4 <= SMEM_GEMM_BYTES, "epi1 fits");
static_assert(128 * ESTR2 * 4 <= SMEM_GEMM_BYTES, "epi2 fits");

// ---- kernel 1: GEMM1 hg = x @ W_hg (fp16 mma), fused c/v + chunk reduce ----
// A tile: x rows m0..m0+127, k-chunk 64.  B tile (N-major smem [n][k]):
// rows 0..63 = whT[n0..n0+63] (hidden), rows 64..127 = whT[2048+n0..] (gate).
__device__ __forceinline__ void g1_load(int tid, int m0, int n0, int kt,
                                        __half* as, __half* bs) {
    const int k0 = kt * BK;
    #pragma unroll
    for (int q = 0; q < 4; q++) {            // A: 128 rows x 128B = 1024 x 16B
        int idx = tid + q * 256;
        int row = idx >> 3, c16 = (idx & 7) * 8;
        cp16(&as[row * STRH + c16], &g_xh[(size_t)(m0 + row) * DDIM + k0 + c16]);
    }
    #pragma unroll
    for (int q = 0; q < 4; q++) {            // B: 128 n-rows x 128B
        int idx = tid + q * 256;
        int row = idx >> 3, c16 = (idx & 7) * 8;
        int grow = (row < 64) ? (n0 + row) : (DI + n0 + (row - 64));
        cp16(&bs[row * STRH + c16], &g_whT[(size_t)grow * DDIM + k0 + c16]);
    }
}

__global__ void __launch_bounds__(256, 2) k_gemm1() {
    const int m0 = blockIdx.y * BM;
    const int n0 = blockIdx.x * 64;
    const int tid = threadIdx.x;
    const int wid = tid >> 5, lane = tid & 31;
    const int wm = wid & 3, wn = wid >> 2;       // 4 x 2 warp grid
    const int grp = lane >> 2, tg = lane & 3;

    extern __shared__ char smraw[];
    __half* As = (__half*)smraw;                 // [2][ATILE]
    __half* Bs = As + 2 * ATILE;                 // [2][BTILE]

    float acc[2][8][4];
    #pragma unroll
    for (int a = 0; a < 2; a++)
        #pragma unroll
        for (int b = 0; b < 8; b++)
            #pragma unroll
            for (int r = 0; r < 4; r++) acc[a][b][r] = 0.f;

    g1_load(tid, m0, n0, 0, As, Bs);
    CP_COMMIT();

    constexpr int NKT = DDIM / BK;               // 16
    #pragma unroll 1
    for (int kt = 0; kt < NKT; kt++) {
        const int buf = kt & 1;
        if (kt + 1 < NKT) {
            g1_load(tid, m0, n0, kt + 1, As + (buf ^ 1) * ATILE, Bs + (buf ^ 1) * BTILE);
            CP_COMMIT();
            CP_WAIT1();
        } else {
            CP_WAIT0();
        }
        __syncthreads();
        const __half* as = As + buf * ATILE;
        const __half* bs = Bs + buf * BTILE;
        #pragma unroll
        for (int ks = 0; ks < 4; ks++) {
            const int k = ks * 16;
            uint32_t a[2][4], b[8][2];
            #pragma unroll
            for (int mm = 0; mm < 2; mm++) {
                int r0 = wm * 32 + mm * 16 + grp;
                a[mm][0] = ldu32(&as[r0 * STRH + k + tg * 2]);
                a[mm][1] = ldu32(&as[(r0 + 8) * STRH + k + tg * 2]);
                a[mm][2] = ldu32(&as[r0 * STRH + k + tg * 2 + 8]);
                a[mm][3] = ldu32(&as[(r0 + 8) * STRH + k + tg * 2 + 8]);
            }
            #pragma unroll
            for (int jn = 0; jn < 8; jn++) {
                int col = ((jn < 4) ? (wn * 32 + jn * 8) : (64 + wn * 32 + (jn - 4) * 8)) + grp;
                b[jn][0] = ldu32(&bs[col * STRH + k + tg * 2]);
                b[jn][1] = ldu32(&bs[col * STRH + k + tg * 2 + 8]);
            }
            #pragma unroll
            for (int mm = 0; mm < 2; mm++)
                #pragma unroll
                for (int jn = 0; jn < 8; jn++)
                    mma_f16(acc[mm][jn], a[mm], b[jn]);
        }
        __syncthreads();
    }

    // ---- epilogue: c/v -> smem (coalesced store + fused chunk reduce) ------
    float* sc = (float*)smraw;            // [128][ESTR1]
    float* sv = sc + 128 * ESTR1;         // [128][ESTR1]
    #pragma unroll
    for (int mm = 0; mm < 2; mm++)
        #pragma unroll
        for (int jn = 0; jn < 4; jn++)
            #pragma unroll
            for (int r = 0; r < 4; r++) {
                float hv = acc[mm][jn][r];
                float gv = acc[mm][jn + 4][r];
                int rl = wm * 32 + mm * 16 + grp + ((r >> 1) << 3);
                int cl = wn * 32 + jn * 8 + tg * 2 + (r & 1);
                float e  = __expf(gv);
                float ci = 1.0f / (1.0f + e);        // sigmoid(-g)
                float z  = 1.0f - ci;                // sigmoid(g)
                float G  = (hv >= 0.0f) ? (hv + 0.5f) : sigmoidf_fast(hv);
                sc[rl * ESTR1 + cl] = ci;
                sv[rl * ESTR1 + cl] = z * G;
            }
    __syncthreads();

    // coalesced float4 writes of the 128x64 c/v tiles
    #pragma unroll
    for (int q = 0; q < 8; q++) {
        int idx = tid + q * 256;               // 0..2047
        int row = idx >> 4, c4 = (idx & 15) * 4;
        float4 vc = *(const float4*)&sc[row * ESTR1 + c4];
        float4 vv = *(const float4*)&sv[row * ESTR1 + c4];
        *(float4*)&g_c[(size_t)(m0 + row) * DI + n0 + c4] = vc;
        *(float4*)&g_v[(size_t)(m0 + row) * DI + n0 + c4] = vv;
    }

    // fused chunk reduce: this tile IS one scan chunk (128 consecutive t)
    {
        const int batch = m0 >> 12;            // m0 / 4096
        const int chunk = (m0 & 4095) >> 7;    // (m0 % 4096) / 128
        #pragma unroll 1
        for (int cc = 0; cc < 8; cc++) {
            const int colL = wid * 8 + cc;     // 8 warps x 8 cols = 64
            float C = 1.f, V = 0.f;
            #pragma unroll
            for (int rb = 0; rb < 4; rb++) {
                float c_ = sc[(rb * 32 + lane) * ESTR1 + colL];
                float v_ = sv[(rb * 32 + lane) * ESTR1 + colL];
                // order-preserving tree reduce over 32 lanes (lane = time order)
                #pragma unroll
                for (int off = 1; off < 32; off <<= 1) {
                    float ch = __shfl_down_sync(0xffffffffu, c_, off);
                    float vh = __shfl_down_sync(0xffffffffu, v_, off);
                    v_ = fmaf(ch, v_, vh);     // later o earlier
                    c_ *= ch;
                }
                c_ = __shfl_sync(0xffffffffu, c_, 0);
                v_ = __shfl_sync(0xffffffffu, v_, 0);
                V = fmaf(c_, V, v_);
                C *= c_;
            }
            if (lane == 0) {
                int ch = batch * DI + n0 + colL;
                g_chC[ch * NCHUNK + chunk] = C;
                g_chV[ch * NCHUNK + chunk] = V;
            }
        }
    }
}

// ---- kernel 3: scan over chunk aggregates -> chunk start states ------------
__global__ void k_chunk_scan(const float* __restrict__ prev_hidden) {
    int ch = blockIdx.x * blockDim.x + threadIdx.x;
    if (ch >= NCHAN) return;
    float h = fmaxf(prev_hidden[ch], 1e-8f);
    #pragma unroll
    for (int k = 0; k < NCHUNK; k++) {
        g_hst[ch * NCHUNK + k] = h;
        h = fmaf(g_chC[ch * NCHUNK + k], h, g_chV[ch * NCHUNK + k]);
    }
}

// ---- kernel 4: replay, write h (fp16 rne) + next_hidden --------------------
__global__ void k_scan_apply(float* __restrict__ next_hidden) {
    int ch = blockIdx.x * blockDim.x + threadIdx.x;
    int chunk = blockIdx.y;
    int b = ch >> 11, j = ch & (DI - 1);
    size_t base = ((size_t)(b * TSEQ + chunk * CHLEN)) * DI + j;
    float h = g_hst[ch * NCHUNK + chunk];
    #pragma unroll 4
    for (int t = 0; t < CHLEN; t++) {
        size_t o = base + (size_t)t * DI;
        h = fmaf(g_c[o], h, g_v[o]);
        g_hh[o] = __float2half_rn(h);
    }
    if (chunk == NCHUNK - 1) next_hidden[ch] = h;
}

// ---- kernel 5: GEMM2 out = h @ W_out (fp16 mma) ----------------------------
__device__ __forceinline__ void g2_load(int tid, int m0, int n0, int kt,
                                        __half* as, __half* bs) {
    const int k0 = kt * BK;
    #pragma unroll
    for (int q = 0; q < 4; q++) {
        int idx = tid + q * 256;
        int row = idx >> 3, c16 = (idx & 7) * 8;
        cp16(&as[row * STRH + c16], &g_hh[(size_t)(m0 + row) * DI + k0 + c16]);
    }
    #pragma unroll
    for (int q = 0; q < 4; q++) {
        int idx = tid + q * 256;
        int row = idx >> 3, c16 = (idx & 7) * 8;
        cp16(&bs[row * STRH + c16], &g_woT[(size_t)(n0 + row) * DI + k0 + c16]);
    }
}

__global__ void __launch_bounds__(256, 2) k_gemm2(float* __restrict__ out) {
    const int m0 = blockIdx.y * BM;
    const int n0 = blockIdx.x * 128;
    const int tid = threadIdx.x;
    const int wid = tid >> 5, lane = tid & 31;
    const int wm = wid & 3, wn = wid >> 2;
    const int grp = lane >> 2, tg = lane & 3;

    extern __shared__ char smraw[];
    __half* As = (__half*)smraw;
    __half* Bs = As + 2 * ATILE;

    float acc[2][8][4];
    #pragma unroll
    for (int a = 0; a < 2; a++)
        #pragma unroll
        for (int b = 0; b < 8; b++)
            #pragma unroll
            for (int r = 0; r < 4; r++) acc[a][b][r] = 0.f;

    g2_load(tid, m0, n0, 0, As, Bs);
    CP_COMMIT();

    constexpr int NKT = DI / BK;                 // 32
    #pragma unroll 1
    for (int kt = 0; kt < NKT; kt++) {
        const int buf = kt & 1;
        if (kt + 1 < NKT) {
            g2_load(tid, m0, n0, kt + 1, As + (buf ^ 1) * ATILE, Bs + (buf ^ 1) * BTILE);
            CP_COMMIT();
            CP_WAIT1();
        } else {
            CP_WAIT0();
        }
        __syncthreads();
        const __half* as = As + buf * ATILE;
        const __half* bs = Bs + buf * BTILE;
        #pragma unroll
        for (int ks = 0; ks < 4; ks++) {
            const int k = ks * 16;
            uint32_t a[2][4], b[8][2];
            #pragma unroll
            for (int mm = 0; mm < 2; mm++) {
                int r0 = wm * 32 + mm * 16 + grp;
                a[mm][0] = ldu32(&as[r0 * STRH + k + tg * 2]);
                a[mm][1] = ldu32(&as[(r0 + 8) * STRH + k + tg * 2]);
                a[mm][2] = ldu32(&as[r0 * STRH + k + tg * 2 + 8]);
                a[mm][3] = ldu32(&as[(r0 + 8) * STRH + k + tg * 2 + 8]);
            }
            #pragma unroll
            for (int jn = 0; jn < 8; jn++) {
                int col = wn * 64 + jn * 8 + grp;
                b[jn][0] = ldu32(&bs[col * STRH + k + tg * 2]);
                b[jn][1] = ldu32(&bs[col * STRH + k + tg * 2 + 8]);
            }
            #pragma unroll
            for (int mm = 0; mm < 2; mm++)
                #pragma unroll
                for (int jn = 0; jn < 8; jn++)
                    mma_f16(acc[mm][jn], a[mm], b[jn]);
        }
        __syncthreads();
    }

    // ---- epilogue: stage 128x128 tile in smem, coalesced float4 stores -----
    float* so = (float*)smraw;                 // [128][ESTR2]
    #pragma unroll
    for (int mm = 0; mm < 2; mm++)
        #pragma unroll
        for (int jn = 0; jn < 8; jn++)
            #pragma unroll
            for (int r = 0; r < 4; r++) {
                int rl = wm * 32 + mm * 16 + grp + ((r >> 1) << 3);
                int cl = wn * 64 + jn * 8 + tg * 2 + (r & 1);
                so[rl * ESTR2 + cl] = acc[mm][jn][r];
            }
    __syncthreads();
    #pragma unroll
    for (int q = 0; q < 16; q++) {
        int idx = tid + q * 256;               // 0..4095
        int row = idx >> 5, c4 = (idx & 31) * 4;
        float4 vv = *(const float4*)&so[row * ESTR2 + c4];
        *(float4*)&out[(size_t)(m0 + row) * DDIM + n0 + c4] = vv;
    }
}

// ---------------------------------------------------------------------------
extern "C" void kernel_launch(void* const* d_in, const int* in_sizes, int n_in,
                              void* d_out, int out_size) {
    const float* x    = (const float*)d_in[0];   // (4, 4096, 1024)
    const float* prev = (const float*)d_in[1];   // (4, 2048)
    const float* whg  = (const float*)d_in[2];   // (1024, 4096)
    const float* wout = (const float*)d_in[3];   // (2048, 1024)
    float* out = (float*)d_out;                  // out (16777216) + next_hidden (8192)
    float* next_hidden = out + (size_t)MROWS * DDIM;

    cudaFuncSetAttribute(k_gemm1, cudaFuncAttributeMaxDynamicSharedMemorySize, SMEM_GEMM_BYTES);
    cudaFuncSetAttribute(k_gemm2, cudaFuncAttributeMaxDynamicSharedMemorySize, SMEM_GEMM_BYTES);

    // 0) fp16 conversions (rne) + weight transposes to N-major
    k_conv_x<<<(MROWS * DDIM / 8) / 256, 256>>>((const float4*)x);
    {
        dim3 b(32, 8);
        k_trans_whg <<<dim3(2 * DI / 32, DDIM / 32), b>>>(whg);
        k_trans_wout<<<dim3(DDIM / 32,  DI / 32),   b>>>(wout);
    }
    // 1) GEMM1 (fp16 mma) + c/v epilogue + fused per-chunk affine reduce
    {
        dim3 grid(DI / 64, MROWS / BM);          // 32 x 128
        k_gemm1<<<grid, 256, SMEM_GEMM_BYTES>>>();
    }
    // 2) chunk-aggregate scan
    k_chunk_scan<<<NCHAN / 256, 256>>>(prev);
    // 3) replay -> h (fp16), next_hidden
    {
        dim3 grid(NCHAN / 256, NCHUNK);
        k_scan_apply<<<grid, 256>>>(next_hidden);
    }
    // 4) GEMM2 (fp16 mma) -> out
    {
        dim3 grid(DDIM / 128, MROWS / BM);       // 8 x 128
        k_gemm2<<<grid, 256, SMEM_GEMM_BYTES>>>(out);
    }
}

// round 8
// speedup vs baseline: 1.9725x; 1.0190x over previous
#include <cuda_runtime.h>
#include <cuda_fp16.h>
#include <cstdint>

// ---------------------------------------------------------------------------
// MinGRU layer: B=4, T=4096, D=1024, Di=2048   (legacy mma.sync fp16 path —
// harness compiles via compute_103 virtual arch, so tcgen05 is unavailable)
//   hg = x @ W_hg ; c = sigmoid(-gate); v = sigmoid(gate)*G(hidden)
//   h_t = c_t*h_{t-1} + v_t, h_{-1} = max(prev_hidden, 1e-8)
//   out = h @ W_out ; next_hidden = h[:, T-1]
// R8: 64x64 warp tiles (4 warps/CTA) to cut smem crossbar traffic 33%,
//     ldmatrix.x4 fragment loads to keep issue pressure low.
// ---------------------------------------------------------------------------

constexpr int BBATCH = 4;
constexpr int TSEQ   = 4096;
constexpr int DDIM   = 1024;
constexpr int DI     = 2048;
constexpr int MROWS  = BBATCH * TSEQ;      // 16384
constexpr int NCHUNK = 32;
constexpr int CHLEN  = TSEQ / NCHUNK;      // 128 == GEMM1 M-tile
constexpr int NCHAN  = BBATCH * DI;        // 8192

// ---- scratch (static __device__ globals; no allocation) --------------------
__device__ __half g_xh [(size_t)MROWS * DDIM];      //  32 MB  fp16 x
__device__ __half g_whT[(size_t)(2 * DI) * DDIM];   //   8 MB  W_hg^T fp16 [4096][1024]
__device__ __half g_woT[(size_t)DDIM * DI];         //   4 MB  W_out^T fp16 [1024][2048]
__device__ float  g_c  [(size_t)MROWS * DI];        // 128 MB
__device__ float  g_v  [(size_t)MROWS * DI];        // 128 MB
__device__ __half g_hh [(size_t)MROWS * DI];        //  64 MB  fp16 h
__device__ float  g_chC[NCHAN * NCHUNK];
__device__ float  g_chV[NCHAN * NCHUNK];
__device__ float  g_hst[NCHAN * NCHUNK];

// ---- helpers ---------------------------------------------------------------
__device__ __forceinline__ void cp16(const __half* dst_smem, const __half* src_gmem) {
    uint32_t a = (uint32_t)__cvta_generic_to_shared(dst_smem);
    asm volatile("cp.async.ca.shared.global [%0], [%1], 16;\n" :: "r"(a), "l"(src_gmem));
}
#define CP_COMMIT() asm volatile("cp.async.commit_group;\n")
#define CP_WAIT1()  asm volatile("cp.async.wait_group 1;\n")
#define CP_WAIT0()  asm volatile("cp.async.wait_group 0;\n")

__device__ __forceinline__ void mma_f16(float d[4], const uint32_t a[4], const uint32_t b[2]) {
    asm volatile(
        "mma.sync.aligned.m16n8k16.row.col.f32.f16.f16.f32 "
        "{%0,%1,%2,%3}, {%4,%5,%6,%7}, {%8,%9}, {%0,%1,%2,%3};\n"
        : "+f"(d[0]), "+f"(d[1]), "+f"(d[2]), "+f"(d[3])
        : "r"(a[0]), "r"(a[1]), "r"(a[2]), "r"(a[3]), "r"(b[0]), "r"(b[1]));
}

__device__ __forceinline__ void ldsm4(uint32_t r[4], const __half* p) {
    uint32_t a = (uint32_t)__cvta_generic_to_shared(p);
    asm volatile("ldmatrix.sync.aligned.m8n8.x4.shared.b16 {%0,%1,%2,%3}, [%4];"
                 : "=r"(r[0]), "=r"(r[1]), "=r"(r[2]), "=r"(r[3]) : "r"(a));
}

__device__ __forceinline__ float sigmoidf_fast(float x) {
    return 1.0f / (1.0f + __expf(-x));
}

// ---- kernel 0a: x fp32 -> fp16 (rne) ---------------------------------------
__global__ void k_conv_x(const float4* __restrict__ x) {
    int i = blockIdx.x * blockDim.x + threadIdx.x;   // handles 8 floats
    float4 a = x[2 * i], b = x[2 * i + 1];
    __half2 h0 = __floats2half2_rn(a.x, a.y);
    __half2 h1 = __floats2half2_rn(a.z, a.w);
    __half2 h2 = __floats2half2_rn(b.x, b.y);
    __half2 h3 = __floats2half2_rn(b.z, b.w);
    uint4 o;
    o.x = *(uint32_t*)&h0; o.y = *(uint32_t*)&h1;
    o.z = *(uint32_t*)&h2; o.w = *(uint32_t*)&h3;
    ((uint4*)g_xh)[i] = o;
}

// ---- kernel 0b/0c: weight transpose + fp16 convert -------------------------
__global__ void k_trans_whg(const float* __restrict__ w) {   // [1024][4096] -> [4096][1024]
    __shared__ float t[32][33];
    int bx = blockIdx.x * 32, by = blockIdx.y * 32;
    int x = threadIdx.x, y = threadIdx.y;
    #pragma unroll
    for (int i = 0; i < 32; i += 8)
        t[y + i][x] = w[(size_t)(by + y + i) * (2 * DI) + bx + x];
    __syncthreads();
    #pragma unroll
    for (int i = 0; i < 32; i += 8)
        g_whT[(size_t)(bx + y + i) * DDIM + by + x] = __float2half_rn(t[x][y + i]);
}

__global__ void k_trans_wout(const float* __restrict__ w) {  // [2048][1024] -> [1024][2048]
    __shared__ float t[32][33];
    int bx = blockIdx.x * 32, by = blockIdx.y * 32;
    int x = threadIdx.x, y = threadIdx.y;
    #pragma unroll
    for (int i = 0; i < 32; i += 8)
        t[y + i][x] = w[(size_t)(by + y + i) * DDIM + bx + x];
    __syncthreads();
    #pragma unroll
    for (int i = 0; i < 32; i += 8)
        g_woT[(size_t)(bx + y + i) * DI + by + x] = __float2half_rn(t[x][y + i]);
}

// ---- GEMM tiling constants --------------------------------------------------
constexpr int BM    = 128;
constexpr int BK    = 64;                       // halves per k-tile
constexpr int STRH  = 72;                       // smem row stride in halves (144B, conflict-free)
constexpr int ATILE = BM * STRH;                // halves per A buffer
constexpr int BTILE = 128 * STRH;               // halves per B buffer (128 n-rows)
constexpr int SMEM_GEMM_BYTES = 2 * (ATILE + BTILE) * 2;  // 73728
// epilogue staging (reuses the same dynamic smem):
constexpr int ESTR1 = 68;   // 128x64 c + v tiles (floats)
constexpr int ESTR2 = 132;  // 128x128 out tile  (floats)
static_assert(2 * 128 * ESTR1 * 4 <= SMEM_GEMM_BYTES, "epi1 fits");
static_assert(128 * ESTR2 * 4 <= SMEM_GEMM_BYTES, "epi2 fits");

// ---- kernel 1: GEMM1 hg = x @ W_hg (fp16 mma), fused c/v + chunk reduce ----
// CTA: 128 rows x 64 channels. 4 warps, warp tile 64x64 (2x2 warp grid).
// B smem rows (N-major [n][k]): 0-31 hid(n0..n0+31), 32-63 gate(n0..n0+31),
//                               64-95 hid(n0+32..), 96-127 gate(n0+32..)
// so each warp's 64 B-rows = 32 hidden + 32 gate of the SAME channels.
__device__ __forceinline__ void g1_load(int tid, int m0, int n0, int kt,
                                        __half* as, __half* bs) {
    const int k0 = kt * BK;
    #pragma unroll
    for (int q = 0; q < 8; q++) {            // A: 128 rows x 128B = 1024 x 16B
        int idx = tid + q * 128;
        int row = idx >> 3, c16 = (idx & 7) * 8;
        cp16(&as[row * STRH + c16], &g_xh[(size_t)(m0 + row) * DDIM + k0 + c16]);
    }
    #pragma unroll
    for (int q = 0; q < 8; q++) {            // B: 128 n-rows x 128B
        int idx = tid + q * 128;
        int row = idx >> 3, c16 = (idx & 7) * 8;
        int base = n0 + ((row >> 6) << 5) + (row & 31);
        int grow = ((row >> 5) & 1) ? (DI + base) : base;
        cp16(&bs[row * STRH + c16], &g_whT[(size_t)grow * DDIM + k0 + c16]);
    }
}

__global__ void __launch_bounds__(128, 2) k_gemm1() {
    const int m0 = blockIdx.y * BM;
    const int n0 = blockIdx.x * 64;
    const int tid = threadIdx.x;
    const int wid = tid >> 5, lane = tid & 31;
    const int wm = wid & 1, wn = wid >> 1;       // 2 x 2 warp grid
    const int grp = lane >> 2, tg = lane & 3;

    extern __shared__ char smraw[];
    __half* As = (__half*)smraw;                 // [2][ATILE]
    __half* Bs = As + 2 * ATILE;                 // [2][BTILE]

    float acc[4][8][4];
    #pragma unroll
    for (int a = 0; a < 4; a++)
        #pragma unroll
        for (int b = 0; b < 8; b++)
            #pragma unroll
            for (int r = 0; r < 4; r++) acc[a][b][r] = 0.f;

    // ldmatrix per-lane source rows/col-offsets
    const int a_row  = wm * 64 + (lane & 15);
    const int a_koff = (lane >> 4) << 3;
    const int b_row  = wn * 64 + (lane & 7) + ((lane >> 4) << 3);
    const int b_koff = ((lane >> 3) & 1) << 3;

    g1_load(tid, m0, n0, 0, As, Bs);
    CP_COMMIT();

    constexpr int NKT = DDIM / BK;               // 16
    #pragma unroll 1
    for (int kt = 0; kt < NKT; kt++) {
        const int buf = kt & 1;
        if (kt + 1 < NKT) {
            g1_load(tid, m0, n0, kt + 1, As + (buf ^ 1) * ATILE, Bs + (buf ^ 1) * BTILE);
            CP_COMMIT();
            CP_WAIT1();
        } else {
            CP_WAIT0();
        }
        __syncthreads();
        const __half* as = As + buf * ATILE;
        const __half* bs = Bs + buf * BTILE;
        #pragma unroll
        for (int ks = 0; ks < 4; ks++) {
            const int k = ks * 16;
            uint32_t a[4][4], b[8][2];
            #pragma unroll
            for (int mm = 0; mm < 4; mm++)
                ldsm4(a[mm], &as[(a_row + mm * 16) * STRH + k + a_koff]);
            #pragma unroll
            for (int jp = 0; jp < 4; jp++) {
                uint32_t t[4];
                ldsm4(t, &bs[(b_row + jp * 16) * STRH + k + b_koff]);
                b[2 * jp][0] = t[0]; b[2 * jp][1] = t[1];
                b[2 * jp + 1][0] = t[2]; b[2 * jp + 1][1] = t[3];
            }
            #pragma unroll
            for (int mm = 0; mm < 4; mm++)
                #pragma unroll
                for (int jn = 0; jn < 8; jn++)
                    mma_f16(acc[mm][jn], a[mm], b[jn]);
        }
        __syncthreads();
    }

    // ---- epilogue: c/v -> smem (coalesced store + fused chunk reduce) ------
    // jn 0-3 = hidden (warp B-rows 0-31), jn 4-7 = gate of same channels.
    float* sc = (float*)smraw;            // [128][ESTR1]
    float* sv = sc + 128 * ESTR1;         // [128][ESTR1]
    #pragma unroll
    for (int mm = 0; mm < 4; mm++)
        #pragma unroll
        for (int jn = 0; jn < 4; jn++)
            #pragma unroll
            for (int r = 0; r < 4; r++) {
                float hv = acc[mm][jn][r];
                float gv = acc[mm][jn + 4][r];
                int rl = wm * 64 + mm * 16 + grp + ((r >> 1) << 3);
                int cl = wn * 32 + jn * 8 + tg * 2 + (r & 1);
                float e  = __expf(gv);
                float ci = 1.0f / (1.0f + e);        // sigmoid(-g)
                float z  = 1.0f - ci;                // sigmoid(g)
                float G  = (hv >= 0.0f) ? (hv + 0.5f) : sigmoidf_fast(hv);
                sc[rl * ESTR1 + cl] = ci;
                sv[rl * ESTR1 + cl] = z * G;
            }
    __syncthreads();

    // coalesced float4 writes of the 128x64 c/v tiles
    #pragma unroll
    for (int q = 0; q < 16; q++) {
        int idx = tid + q * 128;               // 0..2047
        int row = idx >> 4, c4 = (idx & 15) * 4;
        float4 vc = *(const float4*)&sc[row * ESTR1 + c4];
        float4 vv = *(const float4*)&sv[row * ESTR1 + c4];
        *(float4*)&g_c[(size_t)(m0 + row) * DI + n0 + c4] = vc;
        *(float4*)&g_v[(size_t)(m0 + row) * DI + n0 + c4] = vv;
    }

    // fused chunk reduce: this tile IS one scan chunk (128 consecutive t)
    {
        const int batch = m0 >> 12;            // m0 / 4096
        const int chunk = (m0 & 4095) >> 7;    // (m0 % 4096) / 128
        #pragma unroll 1
        for (int cc = 0; cc < 16; cc++) {
            const int colL = wid * 16 + cc;    // 4 warps x 16 cols = 64
            float C = 1.f, V = 0.f;
            #pragma unroll
            for (int rb = 0; rb < 4; rb++) {
                float c_ = sc[(rb * 32 + lane) * ESTR1 + colL];
                float v_ = sv[(rb * 32 + lane) * ESTR1 + colL];
                // order-preserving tree reduce over 32 lanes (lane = time order)
                #pragma unroll
                for (int off = 1; off < 32; off <<= 1) {
                    float ch = __shfl_down_sync(0xffffffffu, c_, off);
                    float vh = __shfl_down_sync(0xffffffffu, v_, off);
                    v_ = fmaf(ch, v_, vh);     // later o earlier
                    c_ *= ch;
                }
                c_ = __shfl_sync(0xffffffffu, c_, 0);
                v_ = __shfl_sync(0xffffffffu, v_, 0);
                V = fmaf(c_, V, v_);
                C *= c_;
            }
            if (lane == 0) {
                int ch = batch * DI + n0 + colL;
                g_chC[ch * NCHUNK + chunk] = C;
                g_chV[ch * NCHUNK + chunk] = V;
            }
        }
    }
}

// ---- kernel 3: scan over chunk aggregates -> chunk start states ------------
__global__ void k_chunk_scan(const float* __restrict__ prev_hidden) {
    int ch = blockIdx.x * blockDim.x + threadIdx.x;
    if (ch >= NCHAN) return;
    float h = fmaxf(prev_hidden[ch], 1e-8f);
    #pragma unroll
    for (int k = 0; k < NCHUNK; k++) {
        g_hst[ch * NCHUNK + k] = h;
        h = fmaf(g_chC[ch * NCHUNK + k], h, g_chV[ch * NCHUNK + k]);
    }
}

// ---- kernel 4: replay, write h (fp16 rne) + next_hidden --------------------
__global__ void k_scan_apply(float* __restrict__ next_hidden) {
    int ch = blockIdx.x * blockDim.x + threadIdx.x;
    int chunk = blockIdx.y;
    int b = ch >> 11, j = ch & (DI - 1);
    size_t base = ((size_t)(b * TSEQ + chunk * CHLEN)) * DI + j;
    float h = g_hst[ch * NCHUNK + chunk];
    #pragma unroll 4
    for (int t = 0; t < CHLEN; t++) {
        size_t o = base + (size_t)t * DI;
        h = fmaf(g_c[o], h, g_v[o]);
        g_hh[o] = __float2half_rn(h);
    }
    if (chunk == NCHUNK - 1) next_hidden[ch] = h;
}

// ---- kernel 5: GEMM2 out = h @ W_out (fp16 mma) ----------------------------
__device__ __forceinline__ void g2_load(int tid, int m0, int n0, int kt,
                                        __half* as, __half* bs) {
    const int k0 = kt * BK;
    #pragma unroll
    for (int q = 0; q < 8; q++) {
        int idx = tid + q * 128;
        int row = idx >> 3, c16 = (idx & 7) * 8;
        cp16(&as[row * STRH + c16], &g_hh[(size_t)(m0 + row) * DI + k0 + c16]);
    }
    #pragma unroll
    for (int q = 0; q < 8; q++) {
        int idx = tid + q * 128;
        int row = idx >> 3, c16 = (idx & 7) * 8;
        cp16(&bs[row * STRH + c16], &g_woT[(size_t)(n0 + row) * DI + k0 + c16]);
    }
}

__global__ void __launch_bounds__(128, 2) k_gemm2(float* __restrict__ out) {
    const int m0 = blockIdx.y * BM;
    const int n0 = blockIdx.x * 128;
    const int tid = threadIdx.x;
    const int wid = tid >> 5, lane = tid & 31;
    const int wm = wid & 1, wn = wid >> 1;       // 2 x 2 warp grid, 64x64 tiles
    const int grp = lane >> 2, tg = lane & 3;

    extern __shared__ char smraw[];
    __half* As = (__half*)smraw;
    __half* Bs = As + 2 * ATILE;

    float acc[4][8][4];
    #pragma unroll
    for (int a = 0; a < 4; a++)
        #pragma unroll
        for (int b = 0; b < 8; b++)
            #pragma unroll
            for (int r = 0; r < 4; r++) acc[a][b][r] = 0.f;

    const int a_row  = wm * 64 + (lane & 15);
    const int a_koff = (lane >> 4) << 3;
    const int b_row  = wn * 64 + (lane & 7) + ((lane >> 4) << 3);
    const int b_koff = ((lane >> 3) & 1) << 3;

    g2_load(tid, m0, n0, 0, As, Bs);
    CP_COMMIT();

    constexpr int NKT = DI / BK;                 // 32
    #pragma unroll 1
    for (int kt = 0; kt < NKT; kt++) {
        const int buf = kt & 1;
        if (kt + 1 < NKT) {
            g2_load(tid, m0, n0, kt + 1, As + (buf ^ 1) * ATILE, Bs + (buf ^ 1) * BTILE);
            CP_COMMIT();
            CP_WAIT1();
        } else {
            CP_WAIT0();
        }
        __syncthreads();
        const __half* as = As + buf * ATILE;
        const __half* bs = Bs + buf * BTILE;
        #pragma unroll
        for (int ks = 0; ks < 4; ks++) {
            const int k = ks * 16;
            uint32_t a[4][4], b[8][2];
            #pragma unroll
            for (int mm = 0; mm < 4; mm++)
                ldsm4(a[mm], &as[(a_row + mm * 16) * STRH + k + a_koff]);
            #pragma unroll
            for (int jp = 0; jp < 4; jp++) {
                uint32_t t[4];
                ldsm4(t, &bs[(b_row + jp * 16) * STRH + k + b_koff]);
                b[2 * jp][0] = t[0]; b[2 * jp][1] = t[1];
                b[2 * jp + 1][0] = t[2]; b[2 * jp + 1][1] = t[3];
            }
            #pragma unroll
            for (int mm = 0; mm < 4; mm++)
                #pragma unroll
                for (int jn = 0; jn < 8; jn++)
                    mma_f16(acc[mm][jn], a[mm], b[jn]);
        }
        __syncthreads();
    }

    // ---- epilogue: stage 128x128 tile in smem, coalesced float4 stores -----
    float* so = (float*)smraw;                 // [128][ESTR2]
    #pragma unroll
    for (int mm = 0; mm < 4; mm++)
        #pragma unroll
        for (int jn = 0; jn < 8; jn++)
            #pragma unroll
            for (int r = 0; r < 4; r++) {
                int rl = wm * 64 + mm * 16 + grp + ((r >> 1) << 3);
                int cl = wn * 64 + jn * 8 + tg * 2 + (r & 1);
                so[rl * ESTR2 + cl] = acc[mm][jn][r];
            }
    __syncthreads();
    #pragma unroll
    for (int q = 0; q < 32; q++) {
        int idx = tid + q * 128;               // 0..4095
        int row = idx >> 5, c4 = (idx & 31) * 4;
        float4 vv = *(const float4*)&so[row * ESTR2 + c4];
        *(float4*)&out[(size_t)(m0 + row) * DDIM + n0 + c4] = vv;
    }
}

// ---------------------------------------------------------------------------
extern "C" void kernel_launch(void* const* d_in, const int* in_sizes, int n_in,
                              void* d_out, int out_size) {
    const float* x    = (const float*)d_in[0];   // (4, 4096, 1024)
    const float* prev = (const float*)d_in[1];   // (4, 2048)
    const float* whg  = (const float*)d_in[2];   // (1024, 4096)
    const float* wout = (const float*)d_in[3];   // (2048, 1024)
    float* out = (float*)d_out;                  // out (16777216) + next_hidden (8192)
    float* next_hidden = out + (size_t)MROWS * DDIM;

    cudaFuncSetAttribute(k_gemm1, cudaFuncAttributeMaxDynamicSharedMemorySize, SMEM_GEMM_BYTES);
    cudaFuncSetAttribute(k_gemm2, cudaFuncAttributeMaxDynamicSharedMemorySize, SMEM_GEMM_BYTES);

    // 0) fp16 conversions (rne) + weight transposes to N-major
    k_conv_x<<<(MROWS * DDIM / 8) / 256, 256>>>((const float4*)x);
    {
        dim3 b(32, 8);
        k_trans_whg <<<dim3(2 * DI / 32, DDIM / 32), b>>>(whg);
        k_trans_wout<<<dim3(DDIM / 32,  DI / 32),   b>>>(wout);
    }
    // 1) GEMM1 (fp16 mma, 64x64 warp tiles) + c/v epilogue + fused chunk reduce
    {
        dim3 grid(DI / 64, MROWS / BM);          // 32 x 128
        k_gemm1<<<grid, 128, SMEM_GEMM_BYTES>>>();
    }
    // 2) chunk-aggregate scan
    k_chunk_scan<<<NCHAN / 256, 256>>>(prev);
    // 3) replay -> h (fp16), next_hidden
    {
        dim3 grid(NCHAN / 256, NCHUNK);
        k_scan_apply<<<grid, 256>>>(next_hidden);
    }
    // 4) GEMM2 (fp16 mma, 64x64 warp tiles) -> out
    {
        dim3 grid(DDIM / 128, MROWS / BM);       // 8 x 128
        k_gemm2<<<grid, 128, SMEM_GEMM_BYTES>>>(out);
    }
}